// round 16
// baseline (speedup 1.0000x reference)
#include <cuda_runtime.h>
#include <cuda_fp16.h>
#include <cstdint>

#define BATCH   8192
#define OBS     21
#define HID     512
#define OVERALL 5632
#define IN_DIM  5653
#define OUT_DIM 5640
#define ACT     8

// prep element count: Wb0 + Wb + WmTT + WlH
#define PREP_ELEMS (512 * 32 + 10 * 512 * 512 + 8 * 512 + 8 * 5632)
#define PREP_BLOCKS ((PREP_ELEMS + 255) / 256)

// ---------------- device global scratch (no allocs allowed) ----------------
__device__ __align__(16) __half g_Wb0 [512 * 32];          // block0: 512 out x 21->32 k (zero padded)
__device__ __align__(16) __half g_Wb  [10 * 512 * 512];    // blocks 1..10: [j][n][k] k-major
__device__ __align__(16) float  g_WmTT[8 * 512];           // mean block [a][k]
__device__ __align__(16) float  g_WlH [8 * 5632];          // logstd hidden part [a][c]

// ---------------- helpers ----------------
__device__ __forceinline__ uint32_t smem_u32(const void* p) {
    uint32_t a;
    asm("{ .reg .u64 t; cvta.to.shared.u64 t, %1; cvt.u32.u64 %0, t; }" : "=r"(a) : "l"(p));
    return a;
}
__device__ __forceinline__ void cp16(uint32_t dst, const void* src) {
    asm volatile("cp.async.cg.shared.global [%0], [%1], 16;" :: "r"(dst), "l"(src) : "memory");
}
#define CP_COMMIT() asm volatile("cp.async.commit_group;" ::: "memory")
#define CP_WAIT(n)  asm volatile("cp.async.wait_group %0;" :: "n"(n) : "memory")

__device__ __forceinline__ void ldsm4(uint32_t& r0, uint32_t& r1, uint32_t& r2, uint32_t& r3, uint32_t addr) {
    asm volatile("ldmatrix.sync.aligned.m8n8.x4.shared.b16 {%0,%1,%2,%3}, [%4];"
                 : "=r"(r0), "=r"(r1), "=r"(r2), "=r"(r3) : "r"(addr));
}
__device__ __forceinline__ void mma16816(float* c, const uint32_t* a, const uint32_t* b)
{
    asm volatile(
        "mma.sync.aligned.m16n8k16.row.col.f32.f16.f16.f32 "
        "{%0,%1,%2,%3}, {%4,%5,%6,%7}, {%8,%9}, {%0,%1,%2,%3};\n"
        : "+f"(c[0]), "+f"(c[1]), "+f"(c[2]), "+f"(c[3])
        : "r"(a[0]), "r"(a[1]), "r"(a[2]), "r"(a[3]), "r"(b[0]), "r"(b[1]));
}

#define SW128(x) ((x) ^ (((x) >> 3) & 0x70))

// ---------------- prep: pack banded blocks, convert to fp16 ----------------
__global__ void prep_kernel(const float* __restrict__ Wm, const float* __restrict__ Wl)
{
    int idx = blockIdx.x * 256 + threadIdx.x;
    if (idx < 512 * 32) {
        int n = idx >> 5, k = idx & 31;
        g_Wb0[idx] = __float2half_rn(k < OBS ? Wm[n * IN_DIM + k] : 0.f);
        return;
    }
    idx -= 512 * 32;
    if (idx < 10 * 512 * 512) {
        int j   = idx >> 18;
        int rem = idx & 262143;
        int n   = rem >> 9, k = rem & 511;
        g_Wb[idx] = __float2half_rn(Wm[(size_t)(512 * (j + 1) + n) * IN_DIM + (OBS + 512 * j + k)]);
        return;
    }
    idx -= 10 * 512 * 512;
    if (idx < 8 * 512) {
        int a = idx >> 9, k = idx & 511;
        g_WmTT[idx] = Wm[(size_t)(OVERALL + a) * IN_DIM + (IN_DIM - 512) + k];
        return;
    }
    idx -= 8 * 512;
    if (idx < 8 * 5632) {
        int a = idx / 5632, c = idx - a * 5632;
        g_WlH[idx] = Wl[(size_t)a * IN_DIM + OBS + c];
    }
}

// ---------------- main banded GEMM: fp32 A loaded+converted in-loop, no xh pass ----------------
// CTA 128x128 (8 warps of 64x32, 2 CTAs/SM); A: LDG.128 fp32 -> cvt -> STS, 3 smem buffers;
// B: fp16 cp.async, 3 stages; ONE __syncthreads per k-slice.
#define NST      3
#define SLICES   8
#define AB_BYTES (128 * 128)   // 16KB per buffer/stage (fp16, 128 rows x 128B)
#define SMEM_DYN (1024 + 6 * AB_BYTES + 512)

__global__ __launch_bounds__(256, 2) void gemm_mma(
    const float* __restrict__ hidden0, const float* __restrict__ b_mean,
    float* __restrict__ out_hidden)
{
    extern __shared__ char dsm[];
    const uint32_t sb = (smem_u32(dsm) + 1023) & ~1023u;
    const int tid  = threadIdx.x;
    const int warp = tid >> 5, lane = tid & 31;
    const int gid  = lane >> 2, tig = lane & 3;
    const int warpM = warp >> 2, warpN = warp & 3;
    const int j     = blockIdx.z;
    const int mbase = blockIdx.y * 128;
    const int nbase = blockIdx.x * 128;
    const int colbase = (j + 1) * 512 + nbase;

    uint32_t Abuf[NST], Bbuf[NST];
#pragma unroll
    for (int s = 0; s < NST; s++) { Abuf[s] = sb + s * AB_BYTES; Bbuf[s] = sb + (NST + s) * AB_BYTES; }
    float* bias_s = (float*)(dsm + (sb + 6 * AB_BYTES - smem_u32(dsm)));
    if (tid < 128) bias_s[tid] = b_mean[colbase + tid];

    const float*  Asrc = hidden0 + (size_t)mbase * OVERALL + j * 512;
    const __half* Bsrc = g_Wb + (size_t)j * 512 * 512 + (size_t)nbase * 512;

    // A staging: idx = i*256+tid -> row = idx>>3 (128 rows), hc = idx&7 (8 fp16 = 16B chunk)
    uint4 a_half[4];
    auto loadA = [&](int s) {
#pragma unroll
        for (int i = 0; i < 4; i++) {
            int idx = i * 256 + tid;
            int row = idx >> 3, hc = idx & 7;
            const float* g = Asrc + (size_t)row * OVERALL + s * 64 + hc * 8;
            float4 v0 = ((const float4*)g)[0];
            float4 v1 = ((const float4*)g)[1];
            __half2 h0 = __floats2half2_rn(v0.x, v0.y);
            __half2 h1 = __floats2half2_rn(v0.z, v0.w);
            __half2 h2 = __floats2half2_rn(v1.x, v1.y);
            __half2 h3 = __floats2half2_rn(v1.z, v1.w);
            a_half[i].x = *(uint32_t*)&h0; a_half[i].y = *(uint32_t*)&h1;
            a_half[i].z = *(uint32_t*)&h2; a_half[i].w = *(uint32_t*)&h3;
        }
    };
    auto stsA = [&](int s) {
        uint32_t base = Abuf[s % NST];
#pragma unroll
        for (int i = 0; i < 4; i++) {
            int idx = i * 256 + tid;
            int row = idx >> 3, hc = idx & 7;
            *(uint4*)(dsm + (base + SW128(row * 128 + hc * 16) - smem_u32(dsm))) = a_half[i];
        }
    };
    auto cpB = [&](int s) {
        uint32_t base = Bbuf[s % NST];
#pragma unroll
        for (int i = 0; i < 4; i++) {
            int idx = i * 256 + tid;
            int row = idx >> 3, hc = idx & 7;
            cp16(base + SW128(row * 128 + hc * 16), Bsrc + (size_t)row * 512 + s * 64 + hc * 8);
        }
        CP_COMMIT();
    };

    float acc[4][4][4];
#pragma unroll
    for (int a = 0; a < 4; a++)
#pragma unroll
        for (int b = 0; b < 4; b++)
#pragma unroll
            for (int e = 0; e < 4; e++) acc[a][b][e] = 0.f;

    const int lrow15 = lane & 15;
    const int klo    = (lane & 16) ? 16 : 0;

    auto compute = [&](int s) {
        uint32_t Ab = Abuf[s % NST], Bb = Bbuf[s % NST];
#pragma unroll
        for (int kk = 0; kk < 4; kk++) {
            uint32_t af[4][4], bf[4][2];
#pragma unroll
            for (int mi = 0; mi < 4; mi++) {
                int row = warpM * 64 + mi * 16 + lrow15;
                ldsm4(af[mi][0], af[mi][1], af[mi][2], af[mi][3],
                      Ab + SW128(row * 128 + kk * 32 + klo));
            }
#pragma unroll
            for (int p = 0; p < 2; p++) {
                int row = warpN * 32 + p * 16 + lrow15;
                uint32_t q0, q1, q2, q3;
                ldsm4(q0, q1, q2, q3, Bb + SW128(row * 128 + kk * 32 + klo));
                bf[2 * p][0] = q0; bf[2 * p + 1][0] = q1;
                bf[2 * p][1] = q2; bf[2 * p + 1][1] = q3;
            }
#pragma unroll
            for (int mi = 0; mi < 4; mi++)
#pragma unroll
                for (int ni = 0; ni < 4; ni++)
                    mma16816(acc[mi][ni], af[mi], bf[ni]);
        }
    };

    // prologue: A bufs 0,1 filled; B stages 0,1 committed
    loadA(0); stsA(0); loadA(1); stsA(1);
    cpB(0); cpB(1);

    // main loop: ONE sync per slice.
    //  - stsA/cpB(t+2) target buffer (t+2)%3 == (t-1)%3: last read by compute(t-1), done pre-barrier.
    //  - loadA issued before compute so LDG latency hides under the MMAs; STS after compute.
#pragma unroll 1
    for (int t = 0; t < SLICES; t++) {
        if (t + 1 < SLICES) CP_WAIT(1);
        else                CP_WAIT(0);
        __syncthreads();
        if (t + 2 < SLICES) { loadA(t + 2); cpB(t + 2); }
        compute(t);
        if (t + 2 < SLICES) stsA(t + 2);
    }

    // epilogue: bias + relu
#pragma unroll
    for (int mi = 0; mi < 4; mi++) {
#pragma unroll
        for (int ni = 0; ni < 4; ni++) {
            int row  = mbase + warpM * 64 + mi * 16 + gid;
            int cloc = warpN * 32 + ni * 8 + tig * 2;
            int colg = colbase + cloc;
            float bv0 = bias_s[cloc], bv1 = bias_s[cloc + 1];
            float2 v0, v1;
            v0.x = fmaxf(acc[mi][ni][0] + bv0, 0.f);
            v0.y = fmaxf(acc[mi][ni][1] + bv1, 0.f);
            v1.x = fmaxf(acc[mi][ni][2] + bv0, 0.f);
            v1.y = fmaxf(acc[mi][ni][3] + bv1, 0.f);
            *(float2*)&out_hidden[(size_t)row * OVERALL + colg]       = v0;
            *(float2*)&out_hidden[(size_t)(row + 8) * OVERALL + colg] = v1;
        }
    }
}

// ---------------- obs chunk GEMM (cols 0..511, K=21) ----------------
__global__ __launch_bounds__(256) void gemm_obs(
    const float* __restrict__ obs, const float* __restrict__ b_mean,
    float* __restrict__ out_hidden)
{
    const int tid  = threadIdx.x;
    const int warp = tid >> 5, lane = tid & 31;
    const int gid  = lane >> 2, tig = lane & 3;
    const int warpM = warp >> 2, warpN = warp & 3;
    const int mbase = blockIdx.y * 128;
    const int nbase = blockIdx.x * 128;

    __shared__ __half As[128][40];
    __shared__ __half Bs[128][40];

    float acc[4][4][4];
#pragma unroll
    for (int a = 0; a < 4; a++)
#pragma unroll
        for (int b = 0; b < 4; b++)
#pragma unroll
            for (int e = 0; e < 4; e++) acc[a][b][e] = 0.f;

    const int ac  = (tid & 7) * 4;
    const int ar0 = tid >> 3;
    const int bsg = (tid & 3) * 8;
    const int br0 = tid >> 2;

#pragma unroll
    for (int i = 0; i < 4; i++) {
        int r = mbase + ar0 + 32 * i;
        __half2* p = (__half2*)&As[ar0 + 32 * i][ac];
        float v0 = (ac + 0 < OBS) ? obs[(size_t)r * OBS + ac + 0] : 0.f;
        float v1 = (ac + 1 < OBS) ? obs[(size_t)r * OBS + ac + 1] : 0.f;
        float v2 = (ac + 2 < OBS) ? obs[(size_t)r * OBS + ac + 2] : 0.f;
        float v3 = (ac + 3 < OBS) ? obs[(size_t)r * OBS + ac + 3] : 0.f;
        p[0] = __floats2half2_rn(v0, v1);
        p[1] = __floats2half2_rn(v2, v3);
    }
#pragma unroll
    for (int i = 0; i < 2; i++)
        *(uint4*)&Bs[br0 + 64 * i][bsg] = *(const uint4*)(g_Wb0 + (size_t)(nbase + br0 + 64 * i) * 32 + bsg);
    __syncthreads();

#pragma unroll
    for (int kk = 0; kk < 2; kk++) {
        const int kc = kk * 16 + tig * 2;
        uint32_t af[4][4], bf[4][2];
#pragma unroll
        for (int mi = 0; mi < 4; mi++) {
            int r = warpM * 64 + mi * 16 + gid;
            af[mi][0] = *(const uint32_t*)&As[r    ][kc    ];
            af[mi][1] = *(const uint32_t*)&As[r + 8][kc    ];
            af[mi][2] = *(const uint32_t*)&As[r    ][kc + 8];
            af[mi][3] = *(const uint32_t*)&As[r + 8][kc + 8];
        }
#pragma unroll
        for (int ni = 0; ni < 4; ni++) {
            int n = warpN * 32 + ni * 8 + gid;
            bf[ni][0] = *(const uint32_t*)&Bs[n][kc    ];
            bf[ni][1] = *(const uint32_t*)&Bs[n][kc + 8];
        }
#pragma unroll
        for (int mi = 0; mi < 4; mi++)
#pragma unroll
            for (int ni = 0; ni < 4; ni++)
                mma16816(acc[mi][ni], af[mi], bf[ni]);
    }

#pragma unroll
    for (int mi = 0; mi < 4; mi++) {
#pragma unroll
        for (int ni = 0; ni < 4; ni++) {
            int row  = mbase + warpM * 64 + mi * 16 + gid;
            int colg = nbase + warpN * 32 + ni * 8 + tig * 2;
            float bv0 = b_mean[colg], bv1 = b_mean[colg + 1];
            float2 v0, v1;
            v0.x = fmaxf(acc[mi][ni][0] + bv0, 0.f);
            v0.y = fmaxf(acc[mi][ni][1] + bv1, 0.f);
            v1.x = fmaxf(acc[mi][ni][2] + bv0, 0.f);
            v1.y = fmaxf(acc[mi][ni][3] + bv1, 0.f);
            *(float2*)&out_hidden[(size_t)row * OVERALL + colg]       = v0;
            *(float2*)&out_hidden[(size_t)(row + 8) * OVERALL + colg] = v1;
        }
    }
}

// ---------------- tail: new_log_std (K=5653,N=8) + new_mean (K=512,N=8), fp32 hidden0 ----------------
__global__ __launch_bounds__(256) void tail_kernel(
    const float* __restrict__ obs, const float* __restrict__ hidden0,
    const float* __restrict__ Wl, const float* __restrict__ b_mean,
    const float* __restrict__ b_logstd,
    float* __restrict__ out_mean, float* __restrict__ out_logstd)
{
    __shared__ float ws[8 * 1024];
    __shared__ float wm[8 * 512];
    const int tid  = threadIdx.x;
    const int warp = tid >> 5, lane = tid & 31;
    const int r0 = (blockIdx.x * 8 + warp) * 2;

    float accL[2][8], accM[2][8];
#pragma unroll
    for (int r = 0; r < 2; r++)
#pragma unroll
        for (int a = 0; a < 8; a++) { accL[r][a] = 0.f; accM[r][a] = 0.f; }

    const float* x0p = hidden0 + (size_t)r0 * OVERALL;
    const float* x1p = hidden0 + (size_t)(r0 + 1) * OVERALL;

#pragma unroll 1
    for (int tt = 0; tt < 6; tt++) {
        const int cnt = (tt < 5) ? 1024 : 512;
        __syncthreads();
        for (int e = tid; e < 8 * cnt; e += 256) {
            int a = e / cnt, cl = e - a * cnt;
            ws[a * 1024 + cl] = g_WlH[a * 5632 + tt * 1024 + cl];
        }
        if (tt == 0) {
            for (int e = tid; e < 8 * 512; e += 256) wm[e] = g_WmTT[e];
        }
        __syncthreads();

        const int iters = cnt >> 7;
#pragma unroll 1
        for (int it = 0; it < iters; it++) {
            int cl = it * 128 + lane * 4;
            int c  = tt * 1024 + cl;
            float4 x0 = *(const float4*)(x0p + c);
            float4 x1 = *(const float4*)(x1p + c);
#pragma unroll
            for (int a = 0; a < 8; a++) {
                float4 w = *(const float4*)&ws[a * 1024 + cl];
                accL[0][a] += x0.x * w.x + x0.y * w.y + x0.z * w.z + x0.w * w.w;
                accL[1][a] += x1.x * w.x + x1.y * w.y + x1.z * w.z + x1.w * w.w;
            }
            if (tt == 5) {
#pragma unroll
                for (int a = 0; a < 8; a++) {
                    float4 w = *(const float4*)&wm[a * 512 + cl];
                    accM[0][a] += x0.x * w.x + x0.y * w.y + x0.z * w.z + x0.w * w.w;
                    accM[1][a] += x1.x * w.x + x1.y * w.y + x1.z * w.z + x1.w * w.w;
                }
            }
        }
    }

    // obs columns (0..20 of x) for logstd
#pragma unroll
    for (int r = 0; r < 2; r++) {
        float xo = (lane < OBS) ? obs[(size_t)(r0 + r) * OBS + lane] : 0.f;
#pragma unroll
        for (int a = 0; a < 8; a++) {
            float w = (lane < OBS) ? __ldg(&Wl[(size_t)a * IN_DIM + lane]) : 0.f;
            accL[r][a] += xo * w;
        }
    }

#pragma unroll
    for (int r = 0; r < 2; r++)
#pragma unroll
        for (int a = 0; a < 8; a++) {
            float v = accL[r][a];
#pragma unroll
            for (int s = 16; s > 0; s >>= 1) v += __shfl_xor_sync(0xffffffffu, v, s);
            accL[r][a] = v;
            float m = accM[r][a];
#pragma unroll
            for (int s = 16; s > 0; s >>= 1) m += __shfl_xor_sync(0xffffffffu, m, s);
            accM[r][a] = m;
        }

    if (lane == 0) {
#pragma unroll
        for (int r = 0; r < 2; r++)
#pragma unroll
            for (int a = 0; a < 8; a++) {
                out_logstd[(size_t)(r0 + r) * 8 + a] = accL[r][a] + b_logstd[a];
                out_mean  [(size_t)(r0 + r) * 8 + a] = accM[r][a] + b_mean[OVERALL + a];
            }
    }
}

// ---------------- elementwise ----------------
__global__ void ew_kernel(const float* __restrict__ pm, const float* __restrict__ pls,
                          float* __restrict__ out_pm, float* __restrict__ out_ls)
{
    int i = blockIdx.x * 256 + threadIdx.x;
    if (i < BATCH * ACT) {
        out_pm[i] = pm[i];
        float t = tanhf(pls[i]);
        out_ls[i] = -5.0f + 3.5f * (t + 1.0f);
    }
}

// ---------------- launch: no xh pass; 1 stream + 3 events (proven guard-safe) ----------------
extern "C" void kernel_launch(void* const* d_in, const int* in_sizes, int n_in,
                              void* d_out, int out_size)
{
    const float* obs         = (const float*)d_in[0];
    const float* hidden0     = (const float*)d_in[1];
    const float* prev_mean   = (const float*)d_in[2];
    const float* prev_logstd = (const float*)d_in[3];
    const float* W_mean      = (const float*)d_in[4];
    const float* b_mean      = (const float*)d_in[5];
    const float* W_logstd    = (const float*)d_in[6];
    const float* b_logstd    = (const float*)d_in[7];

    float* out   = (float*)d_out;
    float* o_pm  = out;                                   // prev_mean      [8192,8]
    float* o_ls  = out + (size_t)BATCH * ACT;             // log_std        [8192,8]
    float* o_h   = o_ls + (size_t)BATCH * ACT;            // new_hidden     [8192,5632]
    float* o_nm  = o_h + (size_t)BATCH * OVERALL;         // new_mean       [8192,8]
    float* o_nls = o_nm + (size_t)BATCH * ACT;            // new_log_std    [8192,8]

    cudaFuncSetAttribute(gemm_mma, cudaFuncAttributeMaxDynamicSharedMemorySize, SMEM_DYN);

    cudaStream_t s1;
    cudaStreamCreateWithFlags(&s1, cudaStreamNonBlocking);
    cudaEvent_t e_fork, e_prep, e_join;
    cudaEventCreateWithFlags(&e_fork, cudaEventDisableTiming);
    cudaEventCreateWithFlags(&e_prep, cudaEventDisableTiming);
    cudaEventCreateWithFlags(&e_join, cudaEventDisableTiming);

    cudaEventRecord(e_fork, 0);
    cudaStreamWaitEvent(s1, e_fork, 0);

    // side stream: prep -> ew -> obs-GEMM -> tail (all hidden under the main GEMM)
    prep_kernel<<<PREP_BLOCKS, 256, 0, s1>>>(W_mean, W_logstd);
    cudaEventRecord(e_prep, s1);
    ew_kernel<<<256, 256, 0, s1>>>(prev_mean, prev_logstd, o_pm, o_ls);
    gemm_obs<<<dim3(4, 64), 256, 0, s1>>>(obs, b_mean, o_h);
    tail_kernel<<<512, 256, 0, s1>>>(obs, hidden0, W_logstd, b_mean, b_logstd, o_nm, o_nls);
    cudaEventRecord(e_join, s1);

    // main stream: GEMM reads fp32 hidden0 directly (no xh pass); waits only for packed weights
    cudaStreamWaitEvent(0, e_prep, 0);
    gemm_mma<<<dim3(4, 64, 10), 256, SMEM_DYN>>>(hidden0, b_mean, o_h);

    cudaStreamWaitEvent(0, e_join, 0);
}

// round 17
// speedup vs baseline: 1.2082x; 1.2082x over previous
#include <cuda_runtime.h>
#include <cuda_fp16.h>
#include <cstdint>

#define BATCH   8192
#define OBS     21
#define HID     512
#define OVERALL 5632
#define IN_DIM  5653
#define OUT_DIM 5640
#define ACT     8

// prep element count: Wb0 + Wb + WmTT + WlH
#define PREP_ELEMS (512 * 32 + 10 * 512 * 512 + 8 * 512 + 8 * 5632)
#define PREP_BLOCKS ((PREP_ELEMS + 255) / 256)

// ---------------- device global scratch (no allocs allowed) ----------------
__device__ __align__(16) __half g_Wb0 [512 * 32];          // block0: 512 out x 21->32 k (zero padded)
__device__ __align__(16) __half g_Wb  [10 * 512 * 512];    // blocks 1..10: [j][n][k] k-major
__device__ __align__(16) float  g_WmTT[8 * 512];           // mean block [a][k]
__device__ __align__(16) float  g_WlH [8 * 5632];          // logstd hidden part [a][c]
__device__ __align__(16) __half g_xh [(size_t)BATCH * OVERALL];  // fp16 copy of hidden0 (ALL cols)

// ---------------- helpers ----------------
__device__ __forceinline__ uint32_t smem_u32(const void* p) {
    uint32_t a;
    asm("{ .reg .u64 t; cvta.to.shared.u64 t, %1; cvt.u32.u64 %0, t; }" : "=r"(a) : "l"(p));
    return a;
}
__device__ __forceinline__ void cp16(uint32_t dst, const void* src) {
    asm volatile("cp.async.cg.shared.global [%0], [%1], 16;" :: "r"(dst), "l"(src) : "memory");
}
#define CP_COMMIT() asm volatile("cp.async.commit_group;" ::: "memory")
#define CP_WAIT(n)  asm volatile("cp.async.wait_group %0;" :: "n"(n) : "memory")

__device__ __forceinline__ void ldsm4(uint32_t& r0, uint32_t& r1, uint32_t& r2, uint32_t& r3, uint32_t addr) {
    asm volatile("ldmatrix.sync.aligned.m8n8.x4.shared.b16 {%0,%1,%2,%3}, [%4];"
                 : "=r"(r0), "=r"(r1), "=r"(r2), "=r"(r3) : "r"(addr));
}
__device__ __forceinline__ void mma16816(float* c, const uint32_t* a, const uint32_t* b)
{
    asm volatile(
        "mma.sync.aligned.m16n8k16.row.col.f32.f16.f16.f32 "
        "{%0,%1,%2,%3}, {%4,%5,%6,%7}, {%8,%9}, {%0,%1,%2,%3};\n"
        : "+f"(c[0]), "+f"(c[1]), "+f"(c[2]), "+f"(c[3])
        : "r"(a[0]), "r"(a[1]), "r"(a[2]), "r"(a[3]), "r"(b[0]), "r"(b[1]));
}

#define SW128(x) ((x) ^ (((x) >> 3) & 0x70))

// ---------------- prep: pack banded blocks, convert to fp16 ----------------
__global__ void prep_kernel(const float* __restrict__ Wm, const float* __restrict__ Wl)
{
    int idx = blockIdx.x * 256 + threadIdx.x;
    if (idx < 512 * 32) {
        int n = idx >> 5, k = idx & 31;
        g_Wb0[idx] = __float2half_rn(k < OBS ? Wm[n * IN_DIM + k] : 0.f);
        return;
    }
    idx -= 512 * 32;
    if (idx < 10 * 512 * 512) {
        int j   = idx >> 18;
        int rem = idx & 262143;
        int n   = rem >> 9, k = rem & 511;
        g_Wb[idx] = __float2half_rn(Wm[(size_t)(512 * (j + 1) + n) * IN_DIM + (OBS + 512 * j + k)]);
        return;
    }
    idx -= 10 * 512 * 512;
    if (idx < 8 * 512) {
        int a = idx >> 9, k = idx & 511;
        g_WmTT[idx] = Wm[(size_t)(OVERALL + a) * IN_DIM + (IN_DIM - 512) + k];
        return;
    }
    idx -= 8 * 512;
    if (idx < 8 * 5632) {
        int a = idx / 5632, c = idx - a * 5632;
        g_WlH[idx] = Wl[(size_t)a * IN_DIM + OBS + c];
    }
}

// ---------------- xh: fp32 hidden0 -> fp16 copy (monolithic, contiguous streaming) ----------------
__global__ void xh_kernel(const float* __restrict__ h)
{
    size_t t = (size_t)blockIdx.x * 256 + threadIdx.x;   // one uint4 (8 halves) per thread
    const float4* p = (const float4*)h + t * 2;
    float4 a = p[0], b = p[1];
    __half2 h0 = __floats2half2_rn(a.x, a.y);
    __half2 h1 = __floats2half2_rn(a.z, a.w);
    __half2 h2 = __floats2half2_rn(b.x, b.y);
    __half2 h3 = __floats2half2_rn(b.z, b.w);
    uint4 o;
    o.x = *(uint32_t*)&h0; o.y = *(uint32_t*)&h1; o.z = *(uint32_t*)&h2; o.w = *(uint32_t*)&h3;
    *(uint4*)(g_xh + t * 8) = o;
}

// ---------------- main banded GEMM: R14 config, FULLY UNROLLED mainloop ----------------
#define NST      3
#define SLICES   8
#define AB_BYTES (128 * 128)   // 16KB per stage (fp16, 128 rows x 128B)
#define SMEM_DYN (1024 + 6 * AB_BYTES + 512)

__global__ __launch_bounds__(256, 2) void gemm_mma(
    const float* __restrict__ b_mean, float* __restrict__ out_hidden)
{
    extern __shared__ char dsm[];
    const uint32_t sb = (smem_u32(dsm) + 1023) & ~1023u;
    const int tid  = threadIdx.x;
    const int warp = tid >> 5, lane = tid & 31;
    const int gid  = lane >> 2, tig = lane & 3;
    const int warpM = warp >> 2, warpN = warp & 3;
    const int j     = blockIdx.z;
    const int mbase = blockIdx.y * 128;
    const int nbase = blockIdx.x * 128;
    const int colbase = (j + 1) * 512 + nbase;

    uint32_t Abuf[NST], Bbuf[NST];
#pragma unroll
    for (int s = 0; s < NST; s++) { Abuf[s] = sb + s * AB_BYTES; Bbuf[s] = sb + (NST + s) * AB_BYTES; }
    float* bias_s = (float*)(dsm + (sb + 6 * AB_BYTES - smem_u32(dsm)));
    if (tid < 128) bias_s[tid] = b_mean[colbase + tid];

    const __half* Asrc = g_xh + (size_t)mbase * OVERALL + j * 512;
    const __half* Bsrc = g_Wb + (size_t)j * 512 * 512 + (size_t)nbase * 512;

    auto cpAB = [&](int s) {
        uint32_t Ab = Abuf[s % NST], Bb = Bbuf[s % NST];
#pragma unroll
        for (int i = 0; i < 4; i++) {
            int idx = i * 256 + tid;
            int row = idx >> 3, hc = idx & 7;
            cp16(Ab + SW128(row * 128 + hc * 16), Asrc + (size_t)row * OVERALL + s * 64 + hc * 8);
        }
#pragma unroll
        for (int i = 0; i < 4; i++) {
            int idx = i * 256 + tid;
            int row = idx >> 3, hc = idx & 7;
            cp16(Bb + SW128(row * 128 + hc * 16), Bsrc + (size_t)row * 512 + s * 64 + hc * 8);
        }
        CP_COMMIT();
    };

    float acc[4][4][4];
#pragma unroll
    for (int a = 0; a < 4; a++)
#pragma unroll
        for (int b = 0; b < 4; b++)
#pragma unroll
            for (int e = 0; e < 4; e++) acc[a][b][e] = 0.f;

    const int lrow15 = lane & 15;
    const int klo    = (lane & 16) ? 16 : 0;

    auto compute = [&](int s) {
        uint32_t Ab = Abuf[s % NST], Bb = Bbuf[s % NST];
#pragma unroll
        for (int kk = 0; kk < 4; kk++) {
            uint32_t af[4][4], bf[4][2];
#pragma unroll
            for (int mi = 0; mi < 4; mi++) {
                int row = warpM * 64 + mi * 16 + lrow15;
                ldsm4(af[mi][0], af[mi][1], af[mi][2], af[mi][3],
                      Ab + SW128(row * 128 + kk * 32 + klo));
            }
#pragma unroll
            for (int p = 0; p < 2; p++) {
                int row = warpN * 32 + p * 16 + lrow15;
                uint32_t q0, q1, q2, q3;
                ldsm4(q0, q1, q2, q3, Bb + SW128(row * 128 + kk * 32 + klo));
                bf[2 * p][0] = q0; bf[2 * p + 1][0] = q1;
                bf[2 * p][1] = q2; bf[2 * p + 1][1] = q3;
            }
#pragma unroll
            for (int mi = 0; mi < 4; mi++)
#pragma unroll
                for (int ni = 0; ni < 4; ni++)
                    mma16816(acc[mi][ni], af[mi], bf[ni]);
        }
    };

    cpAB(0); cpAB(1);

    // main loop FULLY UNROLLED: compile-time wait counts, cross-slice scheduling freedom
#pragma unroll
    for (int t = 0; t < SLICES; t++) {
        if (t + 1 < SLICES) CP_WAIT(1);
        else                CP_WAIT(0);
        __syncthreads();
        if (t + 2 < SLICES) cpAB(t + 2);
        compute(t);
    }

#pragma unroll
    for (int mi = 0; mi < 4; mi++) {
#pragma unroll
        for (int ni = 0; ni < 4; ni++) {
            int row  = mbase + warpM * 64 + mi * 16 + gid;
            int cloc = warpN * 32 + ni * 8 + tig * 2;
            int colg = colbase + cloc;
            float bv0 = bias_s[cloc], bv1 = bias_s[cloc + 1];
            float2 v0, v1;
            v0.x = fmaxf(acc[mi][ni][0] + bv0, 0.f);
            v0.y = fmaxf(acc[mi][ni][1] + bv1, 0.f);
            v1.x = fmaxf(acc[mi][ni][2] + bv0, 0.f);
            v1.y = fmaxf(acc[mi][ni][3] + bv1, 0.f);
            *(float2*)&out_hidden[(size_t)row * OVERALL + colg]       = v0;
            *(float2*)&out_hidden[(size_t)(row + 8) * OVERALL + colg] = v1;
        }
    }
}

// ---------------- obs chunk GEMM (cols 0..511, K=21) ----------------
__global__ __launch_bounds__(256) void gemm_obs(
    const float* __restrict__ obs, const float* __restrict__ b_mean,
    float* __restrict__ out_hidden)
{
    const int tid  = threadIdx.x;
    const int warp = tid >> 5, lane = tid & 31;
    const int gid  = lane >> 2, tig = lane & 3;
    const int warpM = warp >> 2, warpN = warp & 3;
    const int mbase = blockIdx.y * 128;
    const int nbase = blockIdx.x * 128;

    __shared__ __half As[128][40];
    __shared__ __half Bs[128][40];

    float acc[4][4][4];
#pragma unroll
    for (int a = 0; a < 4; a++)
#pragma unroll
        for (int b = 0; b < 4; b++)
#pragma unroll
            for (int e = 0; e < 4; e++) acc[a][b][e] = 0.f;

    const int ac  = (tid & 7) * 4;
    const int ar0 = tid >> 3;
    const int bsg = (tid & 3) * 8;
    const int br0 = tid >> 2;

#pragma unroll
    for (int i = 0; i < 4; i++) {
        int r = mbase + ar0 + 32 * i;
        __half2* p = (__half2*)&As[ar0 + 32 * i][ac];
        float v0 = (ac + 0 < OBS) ? obs[(size_t)r * OBS + ac + 0] : 0.f;
        float v1 = (ac + 1 < OBS) ? obs[(size_t)r * OBS + ac + 1] : 0.f;
        float v2 = (ac + 2 < OBS) ? obs[(size_t)r * OBS + ac + 2] : 0.f;
        float v3 = (ac + 3 < OBS) ? obs[(size_t)r * OBS + ac + 3] : 0.f;
        p[0] = __floats2half2_rn(v0, v1);
        p[1] = __floats2half2_rn(v2, v3);
    }
#pragma unroll
    for (int i = 0; i < 2; i++)
        *(uint4*)&Bs[br0 + 64 * i][bsg] = *(const uint4*)(g_Wb0 + (size_t)(nbase + br0 + 64 * i) * 32 + bsg);
    __syncthreads();

#pragma unroll
    for (int kk = 0; kk < 2; kk++) {
        const int kc = kk * 16 + tig * 2;
        uint32_t af[4][4], bf[4][2];
#pragma unroll
        for (int mi = 0; mi < 4; mi++) {
            int r = warpM * 64 + mi * 16 + gid;
            af[mi][0] = *(const uint32_t*)&As[r    ][kc    ];
            af[mi][1] = *(const uint32_t*)&As[r + 8][kc    ];
            af[mi][2] = *(const uint32_t*)&As[r    ][kc + 8];
            af[mi][3] = *(const uint32_t*)&As[r + 8][kc + 8];
        }
#pragma unroll
        for (int ni = 0; ni < 4; ni++) {
            int n = warpN * 32 + ni * 8 + gid;
            bf[ni][0] = *(const uint32_t*)&Bs[n][kc    ];
            bf[ni][1] = *(const uint32_t*)&Bs[n][kc + 8];
        }
#pragma unroll
        for (int mi = 0; mi < 4; mi++)
#pragma unroll
            for (int ni = 0; ni < 4; ni++)
                mma16816(acc[mi][ni], af[mi], bf[ni]);
    }

#pragma unroll
    for (int mi = 0; mi < 4; mi++) {
#pragma unroll
        for (int ni = 0; ni < 4; ni++) {
            int row  = mbase + warpM * 64 + mi * 16 + gid;
            int colg = nbase + warpN * 32 + ni * 8 + tig * 2;
            float bv0 = b_mean[colg], bv1 = b_mean[colg + 1];
            float2 v0, v1;
            v0.x = fmaxf(acc[mi][ni][0] + bv0, 0.f);
            v0.y = fmaxf(acc[mi][ni][1] + bv1, 0.f);
            v1.x = fmaxf(acc[mi][ni][2] + bv0, 0.f);
            v1.y = fmaxf(acc[mi][ni][3] + bv1, 0.f);
            *(float2*)&out_hidden[(size_t)row * OVERALL + colg]       = v0;
            *(float2*)&out_hidden[(size_t)(row + 8) * OVERALL + colg] = v1;
        }
    }
}

// ---------------- tail: logstd/mean heads, reading fp16 g_xh (half the traffic) ----------------
__global__ __launch_bounds__(256) void tail_kernel(
    const float* __restrict__ obs,
    const float* __restrict__ Wl, const float* __restrict__ b_mean,
    const float* __restrict__ b_logstd,
    float* __restrict__ out_mean, float* __restrict__ out_logstd)
{
    __shared__ float ws[8 * 1024];
    __shared__ float wm[8 * 512];
    const int tid  = threadIdx.x;
    const int warp = tid >> 5, lane = tid & 31;
    const int r0 = (blockIdx.x * 8 + warp) * 2;

    float accL[2][8], accM[2][8];
#pragma unroll
    for (int r = 0; r < 2; r++)
#pragma unroll
        for (int a = 0; a < 8; a++) { accL[r][a] = 0.f; accM[r][a] = 0.f; }

    const __half* x0p = g_xh + (size_t)r0 * OVERALL;
    const __half* x1p = g_xh + (size_t)(r0 + 1) * OVERALL;

#pragma unroll 1
    for (int tt = 0; tt < 6; tt++) {
        const int cnt = (tt < 5) ? 1024 : 512;
        __syncthreads();
        for (int e = tid; e < 8 * cnt; e += 256) {
            int a = e / cnt, cl = e - a * cnt;
            ws[a * 1024 + cl] = g_WlH[a * 5632 + tt * 1024 + cl];
        }
        if (tt == 0) {
            for (int e = tid; e < 8 * 512; e += 256) wm[e] = g_WmTT[e];
        }
        __syncthreads();

        const int iters = cnt >> 7;
#pragma unroll 1
        for (int it = 0; it < iters; it++) {
            int cl = it * 128 + lane * 4;
            int c  = tt * 1024 + cl;
            uint2 u0 = *(const uint2*)(x0p + c);
            uint2 u1 = *(const uint2*)(x1p + c);
            float2 f00 = __half22float2(*(__half2*)&u0.x);
            float2 f01 = __half22float2(*(__half2*)&u0.y);
            float2 f10 = __half22float2(*(__half2*)&u1.x);
            float2 f11 = __half22float2(*(__half2*)&u1.y);
            float4 x0 = make_float4(f00.x, f00.y, f01.x, f01.y);
            float4 x1 = make_float4(f10.x, f10.y, f11.x, f11.y);
#pragma unroll
            for (int a = 0; a < 8; a++) {
                float4 w = *(const float4*)&ws[a * 1024 + cl];
                accL[0][a] += x0.x * w.x + x0.y * w.y + x0.z * w.z + x0.w * w.w;
                accL[1][a] += x1.x * w.x + x1.y * w.y + x1.z * w.z + x1.w * w.w;
            }
            if (tt == 5) {
#pragma unroll
                for (int a = 0; a < 8; a++) {
                    float4 w = *(const float4*)&wm[a * 512 + cl];
                    accM[0][a] += x0.x * w.x + x0.y * w.y + x0.z * w.z + x0.w * w.w;
                    accM[1][a] += x1.x * w.x + x1.y * w.y + x1.z * w.z + x1.w * w.w;
                }
            }
        }
    }

    // obs columns (0..20 of x) for logstd (fp32 path)
#pragma unroll
    for (int r = 0; r < 2; r++) {
        float xo = (lane < OBS) ? obs[(size_t)(r0 + r) * OBS + lane] : 0.f;
#pragma unroll
        for (int a = 0; a < 8; a++) {
            float w = (lane < OBS) ? __ldg(&Wl[(size_t)a * IN_DIM + lane]) : 0.f;
            accL[r][a] += xo * w;
        }
    }

#pragma unroll
    for (int r = 0; r < 2; r++)
#pragma unroll
        for (int a = 0; a < 8; a++) {
            float v = accL[r][a];
#pragma unroll
            for (int s = 16; s > 0; s >>= 1) v += __shfl_xor_sync(0xffffffffu, v, s);
            accL[r][a] = v;
            float m = accM[r][a];
#pragma unroll
            for (int s = 16; s > 0; s >>= 1) m += __shfl_xor_sync(0xffffffffu, m, s);
            accM[r][a] = m;
        }

    if (lane == 0) {
#pragma unroll
        for (int r = 0; r < 2; r++)
#pragma unroll
            for (int a = 0; a < 8; a++) {
                out_logstd[(size_t)(r0 + r) * 8 + a] = accL[r][a] + b_logstd[a];
                out_mean  [(size_t)(r0 + r) * 8 + a] = accM[r][a] + b_mean[OVERALL + a];
            }
    }
}

// ---------------- elementwise ----------------
__global__ void ew_kernel(const float* __restrict__ pm, const float* __restrict__ pls,
                          float* __restrict__ out_pm, float* __restrict__ out_ls)
{
    int i = blockIdx.x * 256 + threadIdx.x;
    if (i < BATCH * ACT) {
        out_pm[i] = pm[i];
        float t = tanhf(pls[i]);
        out_ls[i] = -5.0f + 3.5f * (t + 1.0f);
    }
}

// ---------------- launch: R14 structure (1 stream + 4 events, proven guard-safe) ----------------
extern "C" void kernel_launch(void* const* d_in, const int* in_sizes, int n_in,
                              void* d_out, int out_size)
{
    const float* obs         = (const float*)d_in[0];
    const float* hidden0     = (const float*)d_in[1];
    const float* prev_mean   = (const float*)d_in[2];
    const float* prev_logstd = (const float*)d_in[3];
    const float* W_mean      = (const float*)d_in[4];
    const float* b_mean      = (const float*)d_in[5];
    const float* W_logstd    = (const float*)d_in[6];
    const float* b_logstd    = (const float*)d_in[7];

    float* out   = (float*)d_out;
    float* o_pm  = out;                                   // prev_mean      [8192,8]
    float* o_ls  = out + (size_t)BATCH * ACT;             // log_std        [8192,8]
    float* o_h   = o_ls + (size_t)BATCH * ACT;            // new_hidden     [8192,5632]
    float* o_nm  = o_h + (size_t)BATCH * OVERALL;         // new_mean       [8192,8]
    float* o_nls = o_nm + (size_t)BATCH * ACT;            // new_log_std    [8192,8]

    cudaFuncSetAttribute(gemm_mma, cudaFuncAttributeMaxDynamicSharedMemorySize, SMEM_DYN);

    cudaStream_t s1;
    cudaStreamCreateWithFlags(&s1, cudaStreamNonBlocking);
    cudaEvent_t e_fork, e_prep, e_xh, e_join;
    cudaEventCreateWithFlags(&e_fork, cudaEventDisableTiming);
    cudaEventCreateWithFlags(&e_prep, cudaEventDisableTiming);
    cudaEventCreateWithFlags(&e_xh, cudaEventDisableTiming);
    cudaEventCreateWithFlags(&e_join, cudaEventDisableTiming);

    cudaEventRecord(e_fork, 0);
    cudaStreamWaitEvent(s1, e_fork, 0);

    // s1: prep -> (e_prep) -> ew -> obs-GEMM -> wait xh -> tail (fp16 reads) -> (e_join)
    prep_kernel<<<PREP_BLOCKS, 256, 0, s1>>>(W_mean, W_logstd);
    cudaEventRecord(e_prep, s1);
    ew_kernel<<<256, 256, 0, s1>>>(prev_mean, prev_logstd, o_pm, o_ls);
    gemm_obs<<<dim3(4, 64), 256, 0, s1>>>(obs, b_mean, o_h);
    cudaStreamWaitEvent(s1, e_xh, 0);
    tail_kernel<<<512, 256, 0, s1>>>(obs, W_logstd, b_mean, b_logstd, o_nm, o_nls);
    cudaEventRecord(e_join, s1);

    // s0: xh (monolithic, contiguous) -> (e_xh) -> wait prep -> gemm
    xh_kernel<<<(BATCH * OVERALL / 8 + 255) / 256, 256>>>(hidden0);
    cudaEventRecord(e_xh, 0);
    cudaStreamWaitEvent(0, e_prep, 0);
    gemm_mma<<<dim3(4, 64, 10), 256, SMEM_DYN>>>(b_mean, o_h);

    cudaStreamWaitEvent(0, e_join, 0);
}